// round 1
// baseline (speedup 1.0000x reference)
#include <cuda_runtime.h>

// NeuralBPDecoder: sparse belief propagation.
// H is binary (0.0/1.0) with ~134K nonzeros out of 134M entries.
// Strategy: one pass over H builds ELL adjacency (rows: check->vars,
// cols: var->checks), then 15 iterations of two gather kernels over
// transposed (node-major, batch-minor) state that lives entirely in L2.

#define NC 8192      // checks
#define NV 16384     // vars
#define NB 32        // batch
#define RD 64        // max row degree (Poisson(16.4), P(>=50) ~ 1e-11)
#define CD 48        // max col degree (Poisson(8.2),  P(>=30) ~ 3e-9)
#define ITERS 15

// Scratch (static __device__ globals: no allocation allowed)
__device__ int   g_row_cnt[NC];
__device__ int   g_row_cols[NC * RD];   // 2 MB
__device__ int   g_col_cnt[NV];
__device__ int   g_col_rows[NV * CD];   // 3 MB
__device__ float g_vT[NV * NB];         // 2 MB  beliefs, (v, b)
__device__ float g_cT[NC * NB];         // 1 MB  check messages, (c, b)
__device__ float g_sT[NC * NB];         // 1 MB  syndrome signs, (c, b)
__device__ float g_llrT[NV * NB];       // 2 MB  channel llrs, (v, b)

__global__ void k_zero() {
    int i = blockIdx.x * blockDim.x + threadIdx.x;
    if (i < NC) g_row_cnt[i] = 0;
    if (i < NV) g_col_cnt[i] = 0;
}

// Stream H once (float4 loads), append nonzero coordinates to both ELL lists.
__global__ void k_build(const float4* __restrict__ H4, long n4) {
    long i = (long)blockIdx.x * blockDim.x + threadIdx.x;
    long stride = (long)gridDim.x * blockDim.x;
    for (; i < n4; i += stride) {
        float4 h = H4[i];
        // fast path: all-zero quad (99.6% of quads)
        if (h.x == 0.0f && h.y == 0.0f && h.z == 0.0f && h.w == 0.0f) continue;
        long base = i * 4;
        float vals[4] = {h.x, h.y, h.z, h.w};
        #pragma unroll
        for (int k = 0; k < 4; k++) {
            if (vals[k] != 0.0f) {
                long e = base + k;
                int c = (int)(e >> 14);          // NV = 16384 = 2^14
                int v = (int)(e & (NV - 1));
                int rs = atomicAdd(&g_row_cnt[c], 1);
                if (rs < RD) g_row_cols[c * RD + rs] = v;
                int cs = atomicAdd(&g_col_cnt[v], 1);
                if (cs < CD) g_col_rows[v * CD + cs] = c;
            }
        }
    }
}

// Sort each adjacency list -> deterministic summation order across replays.
__global__ void k_sort() {
    int i = blockIdx.x * blockDim.x + threadIdx.x;
    if (i < NC) {
        int n = min(g_row_cnt[i], RD);
        g_row_cnt[i] = n;
        int* a = &g_row_cols[i * RD];
        for (int j = 1; j < n; j++) {
            int key = a[j]; int k = j - 1;
            while (k >= 0 && a[k] > key) { a[k + 1] = a[k]; k--; }
            a[k + 1] = key;
        }
    }
    if (i < NV) {
        int n = min(g_col_cnt[i], CD);
        g_col_cnt[i] = n;
        int* a = &g_col_rows[i * CD];
        for (int j = 1; j < n; j++) {
            int key = a[j]; int k = j - 1;
            while (k >= 0 && a[k] > key) { a[k + 1] = a[k]; k--; }
            a[k + 1] = key;
        }
    }
}

// Transpose syndrome signs and llrs to node-major; init beliefs = llrs.
__global__ void k_prep(const float* __restrict__ synd,
                       const float* __restrict__ llr) {
    int i = blockIdx.x * blockDim.x + threadIdx.x;
    if (i < NV * NB) {
        int v = i >> 5, b = i & 31;
        float x = llr[b * NV + v];
        g_llrT[i] = x;
        g_vT[i]   = x;
    }
    if (i < NC * NB) {
        int c = i >> 5, b = i & 31;
        g_sT[i] = 1.0f - 2.0f * synd[b * NC + c];
    }
}

// Phase A: v -> c. One warp per check; lane = batch index.
__global__ void k_vc(const float* __restrict__ wvc_p) {
    int t = blockIdx.x * blockDim.x + threadIdx.x;
    int c = t >> 5, lane = t & 31;
    if (c >= NC) return;
    int deg = g_row_cnt[c];
    const int* __restrict__ cols = &g_row_cols[c * RD];
    float acc = 0.0f;
    int j = 0;
    for (; j + 4 <= deg; j += 4) {
        int i0 = cols[j], i1 = cols[j + 1], i2 = cols[j + 2], i3 = cols[j + 3];
        float a0 = g_vT[(i0 << 5) + lane];
        float a1 = g_vT[(i1 << 5) + lane];
        float a2 = g_vT[(i2 << 5) + lane];
        float a3 = g_vT[(i3 << 5) + lane];
        acc += a0; acc += a1; acc += a2; acc += a3;
    }
    for (; j < deg; j++) acc += g_vT[(cols[j] << 5) + lane];
    float wvc = wvc_p[0];
    g_cT[(c << 5) + lane] = g_sT[(c << 5) + lane] * tanhf(0.5f * wvc * acc);
}

// Phase B: c -> v + damped belief update. One warp per var; lane = batch.
__global__ void k_cv(const float* __restrict__ wcv_p,
                     const float* __restrict__ damp_p) {
    int t = blockIdx.x * blockDim.x + threadIdx.x;
    int v = t >> 5, lane = t & 31;
    if (v >= NV) return;
    int deg = g_col_cnt[v];
    const int* __restrict__ rows = &g_col_rows[v * CD];
    float acc = 0.0f;
    int j = 0;
    for (; j + 4 <= deg; j += 4) {
        int i0 = rows[j], i1 = rows[j + 1], i2 = rows[j + 2], i3 = rows[j + 3];
        float a0 = g_cT[(i0 << 5) + lane];
        float a1 = g_cT[(i1 << 5) + lane];
        float a2 = g_cT[(i2 << 5) + lane];
        float a3 = g_cT[(i3 << 5) + lane];
        acc += a0; acc += a1; acc += a2; acc += a3;
    }
    for (; j < deg; j++) acc += g_cT[(rows[j] << 5) + lane];
    float d = damp_p[0];
    float wcv = wcv_p[0];
    int idx = (v << 5) + lane;
    g_vT[idx] = d * g_vT[idx] + (1.0f - d) * (g_llrT[idx] + wcv * acc);
}

// Output: sigmoid(-v), written in (b, v) order.
__global__ void k_out(float* __restrict__ out) {
    int i = blockIdx.x * blockDim.x + threadIdx.x;
    if (i >= NB * NV) return;
    int b = i >> 14, v = i & (NV - 1);
    float x = g_vT[(v << 5) + b];
    out[i] = 1.0f / (1.0f + expf(x));
}

extern "C" void kernel_launch(void* const* d_in, const int* in_sizes, int n_in,
                              void* d_out, int out_size) {
    const float* synd = (const float*)d_in[0];
    const float* H    = (const float*)d_in[1];
    const float* llr  = (const float*)d_in[2];
    const float* wvc  = (const float*)d_in[3];
    const float* wcv  = (const float*)d_in[4];
    const float* damp = (const float*)d_in[5];
    float* out = (float*)d_out;

    k_zero<<<(NV + 255) / 256, 256>>>();
    k_build<<<8192, 256>>>((const float4*)H, (long)NC * NV / 4);
    k_sort<<<(NV + 255) / 256, 256>>>();
    k_prep<<<(NV * NB + 255) / 256, 256>>>(synd, llr);
    for (int it = 0; it < ITERS; it++) {
        k_vc<<<NC * 32 / 256, 256>>>(wvc);
        k_cv<<<NV * 32 / 256, 256>>>(wcv, damp);
    }
    k_out<<<(NB * NV + 255) / 256, 256>>>(out);
}